// round 6
// baseline (speedup 1.0000x reference)
#include <cuda_runtime.h>
#include <cuda_bf16.h>
#include <cstdint>

// Problem constants
#define BB 2
#define HH 16
#define SS 2048
#define DD 128
#define PAD 12   // smem row stride in 32-bit words (conflict-free for frag loads)

// ---------------------------------------------------------------------------
// Helpers: fp32 -> bf16 hi/lo split, packed as bf16x2 words (low half = even k)
// ---------------------------------------------------------------------------
__device__ __forceinline__ uint32_t pack_bf16(__nv_bfloat16 lo16, __nv_bfloat16 hi16) {
    __nv_bfloat162 t;
    t.x = lo16;  // low 16 bits  (even k)
    t.y = hi16;  // high 16 bits (odd k)
    return *reinterpret_cast<uint32_t*>(&t);
}

__device__ __forceinline__ void cvt_pair(float x, float y, uint32_t& whi, uint32_t& wlo) {
    __nv_bfloat16 hx = __float2bfloat16_rn(x);
    __nv_bfloat16 hy = __float2bfloat16_rn(y);
    float fx = __bfloat162float(hx);
    float fy = __bfloat162float(hy);
    whi = pack_bf16(hx, hy);
    wlo = pack_bf16(__float2bfloat16_rn(x - fx), __float2bfloat16_rn(y - fy));
}

// m16n8k16 row.col f32.bf16.bf16.f32 accumulate-in-place
#define MMA16816(C, A, B0, B1)                                                  \
    asm volatile(                                                               \
        "mma.sync.aligned.m16n8k16.row.col.f32.bf16.bf16.f32 "                  \
        "{%0,%1,%2,%3}, {%4,%5,%6,%7}, {%8,%9}, {%0,%1,%2,%3};"                 \
        : "+f"((C)[0]), "+f"((C)[1]), "+f"((C)[2]), "+f"((C)[3])                \
        : "r"((A)[0]), "r"((A)[1]), "r"((A)[2]), "r"((A)[3]),                   \
          "r"(B0), "r"(B1))

// ---------------------------------------------------------------------------
// Kernel 1: raw masked scores -> attn buffer
// scores[b,h,i,j] = scale * dot(q[b,h,i,:], k[b,h,j,:]) + rel_bias[h,i,j]
//                   (or -1e9 where mask[b,0,i,j] == 0)
// Block: 128x128 output tile, 256 threads (8 warps of 32x64).
// ---------------------------------------------------------------------------
__global__ __launch_bounds__(256, 2)
void sdpa_scores_kernel(const float* __restrict__ q, const float* __restrict__ k,
                        const int* __restrict__ mask, const float* __restrict__ bias,
                        float* __restrict__ attn)
{
    __shared__ uint32_t As_hi[128][PAD], As_lo[128][PAD];
    __shared__ uint32_t Bs_hi[128][PAD], Bs_lo[128][PAD];

    const int tid  = threadIdx.x;
    const int warp = tid >> 5, lane = tid & 31;
    const int g = lane >> 2, t = lane & 3;
    const int wm = warp & 3;      // 0..3 -> 32 rows each
    const int wn = warp >> 2;     // 0..1 -> 64 cols each
    const int bh = blockIdx.z;
    const int m_base = blockIdx.y * 128;
    const int n_base = blockIdx.x * 128;

    const float* qb = q + (size_t)bh * SS * DD;
    const float* kb = k + (size_t)bh * SS * DD;

    float acc[2][8][4];
#pragma unroll
    for (int i = 0; i < 2; i++)
#pragma unroll
        for (int j = 0; j < 8; j++)
#pragma unroll
            for (int c = 0; c < 4; c++) acc[i][j][c] = 0.0f;

#pragma unroll 1
    for (int kc = 0; kc < DD / 16; kc++) {
        const int k0 = kc * 16;
        // --- load + convert both tiles (128 rows x 16 k each) ---
#pragma unroll
        for (int i = 0; i < 2; i++) {
            int idx = tid + i * 256;          // 0..511
            int row = idx >> 2, q4 = idx & 3; // 4 float4 per row
            float4 va = *reinterpret_cast<const float4*>(
                qb + (size_t)(m_base + row) * DD + k0 + q4 * 4);
            uint32_t h0, l0, h1, l1;
            cvt_pair(va.x, va.y, h0, l0);
            cvt_pair(va.z, va.w, h1, l1);
            As_hi[row][q4 * 2] = h0; As_hi[row][q4 * 2 + 1] = h1;
            As_lo[row][q4 * 2] = l0; As_lo[row][q4 * 2 + 1] = l1;

            float4 vb = *reinterpret_cast<const float4*>(
                kb + (size_t)(n_base + row) * DD + k0 + q4 * 4);
            cvt_pair(vb.x, vb.y, h0, l0);
            cvt_pair(vb.z, vb.w, h1, l1);
            Bs_hi[row][q4 * 2] = h0; Bs_hi[row][q4 * 2 + 1] = h1;
            Bs_lo[row][q4 * 2] = l0; Bs_lo[row][q4 * 2 + 1] = l1;
        }
        __syncthreads();

        // --- A fragments ---
        uint32_t ah[2][4], al[2][4];
#pragma unroll
        for (int mt = 0; mt < 2; mt++) {
            int r = wm * 32 + mt * 16;
            ah[mt][0] = As_hi[r + g][t];     ah[mt][1] = As_hi[r + g + 8][t];
            ah[mt][2] = As_hi[r + g][t + 4]; ah[mt][3] = As_hi[r + g + 8][t + 4];
            al[mt][0] = As_lo[r + g][t];     al[mt][1] = As_lo[r + g + 8][t];
            al[mt][2] = As_lo[r + g][t + 4]; al[mt][3] = As_lo[r + g + 8][t + 4];
        }
        // --- B fragments + MMAs (hi*hi + hi*lo + lo*hi) ---
#pragma unroll
        for (int nt = 0; nt < 8; nt++) {
            int c = wn * 64 + nt * 8 + g;
            uint32_t bh0 = Bs_hi[c][t], bh1 = Bs_hi[c][t + 4];
            uint32_t bl0 = Bs_lo[c][t], bl1 = Bs_lo[c][t + 4];
#pragma unroll
            for (int mt = 0; mt < 2; mt++) {
                MMA16816(acc[mt][nt], ah[mt], bh0, bh1);
                MMA16816(acc[mt][nt], ah[mt], bl0, bl1);
                MMA16816(acc[mt][nt], al[mt], bh0, bh1);
            }
        }
        __syncthreads();
    }

    // --- epilogue: scale + bias + mask, write raw scores ---
    const int b = bh >> 4, h = bh & 15;
    const float* biasb = bias + (size_t)h * SS * SS;
    const int*   maskb = mask + (size_t)b * SS * SS;
    float*       attnb = attn + (size_t)bh * SS * SS;
    const float scl = 0.08838834764831845f;  // 1/sqrt(128)

#pragma unroll
    for (int mt = 0; mt < 2; mt++) {
#pragma unroll
        for (int nt = 0; nt < 8; nt++) {
            int col  = n_base + wn * 64 + nt * 8 + 2 * t;
            int row0 = m_base + wm * 32 + mt * 16 + g;
#pragma unroll
            for (int half = 0; half < 2; half++) {
                int row = row0 + half * 8;
                float2 bb = *reinterpret_cast<const float2*>(biasb + (size_t)row * SS + col);
                int2   mm = *reinterpret_cast<const int2*>(maskb + (size_t)row * SS + col);
                float s0 = acc[mt][nt][half * 2 + 0] * scl + bb.x;
                float s1 = acc[mt][nt][half * 2 + 1] * scl + bb.y;
                if (mm.x == 0) s0 = -1e9f;
                if (mm.y == 0) s1 = -1e9f;
                *reinterpret_cast<float2*>(attnb + (size_t)row * SS + col) = make_float2(s0, s1);
            }
        }
    }
}

// ---------------------------------------------------------------------------
// Kernel 2: row softmax, in-place on attn buffer. One block (256 thr) per row.
// ---------------------------------------------------------------------------
__global__ __launch_bounds__(256)
void sdpa_softmax_kernel(float* __restrict__ attn)
{
    const size_t row = blockIdx.x;
    float4* p = reinterpret_cast<float4*>(attn + row * SS);
    const int tid = threadIdx.x;
    const int lane = tid & 31, wid = tid >> 5;

    float4 v1 = p[tid];
    float4 v2 = p[tid + 256];

    float m = fmaxf(fmaxf(fmaxf(v1.x, v1.y), fmaxf(v1.z, v1.w)),
                    fmaxf(fmaxf(v2.x, v2.y), fmaxf(v2.z, v2.w)));
#pragma unroll
    for (int o = 16; o > 0; o >>= 1) m = fmaxf(m, __shfl_xor_sync(0xFFFFFFFFu, m, o));

    __shared__ float rmax[8], rsum[8];
    if (lane == 0) rmax[wid] = m;
    __syncthreads();
    m = rmax[0];
#pragma unroll
    for (int j = 1; j < 8; j++) m = fmaxf(m, rmax[j]);

    float e0 = __expf(v1.x - m), e1 = __expf(v1.y - m);
    float e2 = __expf(v1.z - m), e3 = __expf(v1.w - m);
    float e4 = __expf(v2.x - m), e5 = __expf(v2.y - m);
    float e6 = __expf(v2.z - m), e7 = __expf(v2.w - m);

    float s = (e0 + e1) + (e2 + e3) + (e4 + e5) + (e6 + e7);
#pragma unroll
    for (int o = 16; o > 0; o >>= 1) s += __shfl_xor_sync(0xFFFFFFFFu, s, o);
    if (lane == 0) rsum[wid] = s;
    __syncthreads();
    s = rsum[0];
#pragma unroll
    for (int j = 1; j < 8; j++) s += rsum[j];

    float inv = 1.0f / s;
    p[tid]       = make_float4(e0 * inv, e1 * inv, e2 * inv, e3 * inv);
    p[tid + 256] = make_float4(e4 * inv, e5 * inv, e6 * inv, e7 * inv);
}

// ---------------------------------------------------------------------------
// Kernel 3: out = attn @ V. Block: 128 rows x 128 cols (full D), K = 2048.
// V tile staged fp32 (coalesced) then transposed into k-major bf16 split.
// ---------------------------------------------------------------------------
__global__ __launch_bounds__(256, 2)
void sdpa_out_kernel(const float* __restrict__ attn, const float* __restrict__ v,
                     float* __restrict__ out)
{
    __shared__ uint32_t As_hi[128][PAD], As_lo[128][PAD];
    __shared__ uint32_t Bs_hi[128][PAD], Bs_lo[128][PAD];
    __shared__ float    Vstg[16][132];

    const int tid  = threadIdx.x;
    const int warp = tid >> 5, lane = tid & 31;
    const int g = lane >> 2, t = lane & 3;
    const int wm = warp & 3, wn = warp >> 2;
    const int bh = blockIdx.z;
    const int m_base = blockIdx.y * 128;

    const float* ab = attn + (size_t)bh * SS * SS;
    const float* vb = v    + (size_t)bh * SS * DD;

    float acc[2][8][4];
#pragma unroll
    for (int i = 0; i < 2; i++)
#pragma unroll
        for (int j = 0; j < 8; j++)
#pragma unroll
            for (int c = 0; c < 4; c++) acc[i][j][c] = 0.0f;

    const int cn = tid & 127;      // column (n) this thread converts
    const int wh = tid >> 7;       // word-half: words wh*4 .. wh*4+3

#pragma unroll 1
    for (int kc = 0; kc < SS / 16; kc++) {
        const int k0 = kc * 16;
        // --- A tile (attn rows, fp32 -> split) + V staging (coalesced) ---
#pragma unroll
        for (int i = 0; i < 2; i++) {
            int idx = tid + i * 256;
            int row = idx >> 2, q4 = idx & 3;
            float4 va = *reinterpret_cast<const float4*>(
                ab + (size_t)(m_base + row) * SS + k0 + q4 * 4);
            uint32_t h0, l0, h1, l1;
            cvt_pair(va.x, va.y, h0, l0);
            cvt_pair(va.z, va.w, h1, l1);
            As_hi[row][q4 * 2] = h0; As_hi[row][q4 * 2 + 1] = h1;
            As_lo[row][q4 * 2] = l0; As_lo[row][q4 * 2 + 1] = l1;

            int kr = idx >> 5;       // 0..15
            int c4 = idx & 31;       // 0..31
            float4 vv = *reinterpret_cast<const float4*>(
                vb + (size_t)(k0 + kr) * DD + c4 * 4);
            *reinterpret_cast<float4*>(&Vstg[kr][c4 * 4]) = vv;
        }
        __syncthreads();

        // --- transpose-convert V: Bs[n][w] holds k = 2w, 2w+1 for column n ---
#pragma unroll
        for (int w = 0; w < 4; w++) {
            int wrd = wh * 4 + w;
            float x = Vstg[2 * wrd][cn];
            float y = Vstg[2 * wrd + 1][cn];
            uint32_t hw_, lw_;
            cvt_pair(x, y, hw_, lw_);
            Bs_hi[cn][wrd] = hw_;
            Bs_lo[cn][wrd] = lw_;
        }
        __syncthreads();

        uint32_t ah[2][4], al[2][4];
#pragma unroll
        for (int mt = 0; mt < 2; mt++) {
            int r = wm * 32 + mt * 16;
            ah[mt][0] = As_hi[r + g][t];     ah[mt][1] = As_hi[r + g + 8][t];
            ah[mt][2] = As_hi[r + g][t + 4]; ah[mt][3] = As_hi[r + g + 8][t + 4];
            al[mt][0] = As_lo[r + g][t];     al[mt][1] = As_lo[r + g + 8][t];
            al[mt][2] = As_lo[r + g][t + 4]; al[mt][3] = As_lo[r + g + 8][t + 4];
        }
#pragma unroll
        for (int nt = 0; nt < 8; nt++) {
            int c = wn * 64 + nt * 8 + g;
            uint32_t bh0 = Bs_hi[c][t], bh1 = Bs_hi[c][t + 4];
            uint32_t bl0 = Bs_lo[c][t], bl1 = Bs_lo[c][t + 4];
#pragma unroll
            for (int mt = 0; mt < 2; mt++) {
                MMA16816(acc[mt][nt], ah[mt], bh0, bh1);
                MMA16816(acc[mt][nt], ah[mt], bl0, bl1);
                MMA16816(acc[mt][nt], al[mt], bh0, bh1);
            }
        }
        __syncthreads();
    }

    float* ob = out + (size_t)bh * SS * DD;
#pragma unroll
    for (int mt = 0; mt < 2; mt++) {
#pragma unroll
        for (int nt = 0; nt < 8; nt++) {
            int col  = wn * 64 + nt * 8 + 2 * t;
            int row0 = m_base + wm * 32 + mt * 16 + g;
#pragma unroll
            for (int half = 0; half < 2; half++) {
                int row = row0 + half * 8;
                *reinterpret_cast<float2*>(ob + (size_t)row * DD + col) =
                    make_float2(acc[mt][nt][half * 2], acc[mt][nt][half * 2 + 1]);
            }
        }
    }
}

// ---------------------------------------------------------------------------
// Launch
// ---------------------------------------------------------------------------
extern "C" void kernel_launch(void* const* d_in, const int* in_sizes, int n_in,
                              void* d_out, int out_size)
{
    const float* q    = (const float*)d_in[0];
    const float* k    = (const float*)d_in[1];
    const float* v    = (const float*)d_in[2];
    const int*   mask = (const int*)  d_in[3];
    const float* bias = (const float*)d_in[4];

    float* out  = (float*)d_out;                       // [B,H,S,D]
    float* attn = out + (size_t)BB * HH * SS * DD;     // [B,H,S,S]

    dim3 g1(SS / 128, SS / 128, BB * HH);
    sdpa_scores_kernel<<<g1, 256>>>(q, k, mask, bias, attn);

    sdpa_softmax_kernel<<<BB * HH * SS, 256>>>(attn);

    dim3 g3(1, SS / 128, BB * HH);
    sdpa_out_kernel<<<g3, 256>>>(attn, v, out);
}

// round 11
// speedup vs baseline: 1.0625x; 1.0625x over previous
#include <cuda_runtime.h>
#include <cuda_bf16.h>
#include <cstdint>

// Problem constants
#define BB 2
#define HH 16
#define SS 2048
#define DD 128
#define BH (BB*HH)

// ---------------------------------------------------------------------------
// Scratch: precomputed bf16 hi/lo splits (packed k-pairs in uint32 words)
//   g_qh/g_ql, g_kh/g_kl : [bh][s][64 words]   (q pre-scaled by 1/sqrt(D))
//   g_vth/g_vtl          : [bh][d][1024 words] (V transposed, k-major)
// ---------------------------------------------------------------------------
__device__ uint32_t g_qh[(size_t)BH*SS*64];
__device__ uint32_t g_ql[(size_t)BH*SS*64];
__device__ uint32_t g_kh[(size_t)BH*SS*64];
__device__ uint32_t g_kl[(size_t)BH*SS*64];
__device__ uint32_t g_vth[(size_t)BH*DD*(SS/2)];
__device__ uint32_t g_vtl[(size_t)BH*DD*(SS/2)];

// ---------------------------------------------------------------------------
// Helpers
// ---------------------------------------------------------------------------
__device__ __forceinline__ uint32_t pack_bf16(__nv_bfloat16 lo16, __nv_bfloat16 hi16) {
    __nv_bfloat162 t; t.x = lo16; t.y = hi16;
    return *reinterpret_cast<uint32_t*>(&t);
}

__device__ __forceinline__ void cvt_pair(float x, float y, uint32_t& whi, uint32_t& wlo) {
    __nv_bfloat16 hx = __float2bfloat16_rn(x);
    __nv_bfloat16 hy = __float2bfloat16_rn(y);
    float fx = __bfloat162float(hx);
    float fy = __bfloat162float(hy);
    whi = pack_bf16(hx, hy);
    wlo = pack_bf16(__float2bfloat16_rn(x - fx), __float2bfloat16_rn(y - fy));
}

__device__ __forceinline__ uint32_t smaddr(const void* p) {
    return static_cast<uint32_t>(__cvta_generic_to_shared(p));
}

#define MMA16816(C, A, B0, B1)                                                  \
    asm volatile(                                                               \
        "mma.sync.aligned.m16n8k16.row.col.f32.bf16.bf16.f32 "                  \
        "{%0,%1,%2,%3}, {%4,%5,%6,%7}, {%8,%9}, {%0,%1,%2,%3};"                 \
        : "+f"((C)[0]), "+f"((C)[1]), "+f"((C)[2]), "+f"((C)[3])                \
        : "r"((A)[0]), "r"((A)[1]), "r"((A)[2]), "r"((A)[3]),                   \
          "r"(B0), "r"(B1))

__device__ __forceinline__ void ldsm4(uint32_t& r0, uint32_t& r1, uint32_t& r2,
                                      uint32_t& r3, uint32_t addr) {
    asm volatile("ldmatrix.sync.aligned.m8n8.x4.shared.b16 {%0,%1,%2,%3}, [%4];"
                 : "=r"(r0), "=r"(r1), "=r"(r2), "=r"(r3) : "r"(addr));
}

__device__ __forceinline__ void cp16(uint32_t s, const void* g) {
    asm volatile("cp.async.cg.shared.global [%0], [%1], 16;" :: "r"(s), "l"(g) : "memory");
}
#define CP_COMMIT asm volatile("cp.async.commit_group;" ::: "memory")
#define CP_WAIT1  asm volatile("cp.async.wait_group 1;" ::: "memory")
#define CP_WAIT0  asm volatile("cp.async.wait_group 0;" ::: "memory")

// ---------------------------------------------------------------------------
// Precompute 1: split Q (scaled) and K into bf16 hi/lo packed words
// ---------------------------------------------------------------------------
__global__ __launch_bounds__(256)
void split_qk_kernel(const float4* __restrict__ q, const float4* __restrict__ k)
{
    const float scl = 0.08838834764831845f;  // 1/sqrt(128)
    const size_t N4 = (size_t)BH * SS * (DD / 4);
    const size_t stride = (size_t)gridDim.x * blockDim.x;
    for (size_t i = (size_t)blockIdx.x * blockDim.x + threadIdx.x; i < N4; i += stride) {
        uint32_t h0, l0, h1, l1;
        float4 a = q[i];
        cvt_pair(a.x * scl, a.y * scl, h0, l0);
        cvt_pair(a.z * scl, a.w * scl, h1, l1);
        g_qh[2 * i] = h0; g_qh[2 * i + 1] = h1;
        g_ql[2 * i] = l0; g_ql[2 * i + 1] = l1;
        float4 c = k[i];
        cvt_pair(c.x, c.y, h0, l0);
        cvt_pair(c.z, c.w, h1, l1);
        g_kh[2 * i] = h0; g_kh[2 * i + 1] = h1;
        g_kl[2 * i] = l0; g_kl[2 * i + 1] = l1;
    }
}

// ---------------------------------------------------------------------------
// Precompute 2: V -> transposed split (k-major per head-dim row)
// Block handles 64 s-rows x 128 d for one bh.
// ---------------------------------------------------------------------------
__global__ __launch_bounds__(256)
void split_vt_kernel(const float* __restrict__ v)
{
    __shared__ float tile[64][133];
    const int bh = blockIdx.y;
    const int s0 = blockIdx.x * 64;
    const int tid = threadIdx.x;
    const float* vb = v + (size_t)bh * SS * DD + (size_t)s0 * DD;

#pragma unroll
    for (int i = 0; i < 8; i++) {
        int idx = tid + i * 256;
        int r = idx >> 5, c4 = (idx & 31) * 4;
        float4 x = *reinterpret_cast<const float4*>(vb + (size_t)r * DD + c4);
        tile[r][c4 + 0] = x.x; tile[r][c4 + 1] = x.y;
        tile[r][c4 + 2] = x.z; tile[r][c4 + 3] = x.w;
    }
    __syncthreads();

    uint32_t* vh = g_vth + (size_t)bh * DD * (SS / 2) + (s0 >> 1);
    uint32_t* vl = g_vtl + (size_t)bh * DD * (SS / 2) + (s0 >> 1);
#pragma unroll
    for (int i = 0; i < 16; i++) {
        int idx = tid + i * 256;
        int d = idx >> 5, w = idx & 31;
        uint32_t hw_, lw_;
        cvt_pair(tile[2 * w][d], tile[2 * w + 1][d], hw_, lw_);
        vh[(size_t)d * (SS / 2) + w] = hw_;
        vl[(size_t)d * (SS / 2) + w] = lw_;
    }
}

// ---------------------------------------------------------------------------
// Kernel 1: raw masked scores -> attn buffer
// 128x128 tile, 256 threads, k-chunk=32, 2-stage cp.async pipeline, ldmatrix.
// z-order: z = 2h + b so adjacent slabs share rel_bias[h] in L2.
// ---------------------------------------------------------------------------
__global__ __launch_bounds__(256, 2)
void sdpa_scores2_kernel(const int* __restrict__ mask, const float* __restrict__ bias,
                         float* __restrict__ attn)
{
    extern __shared__ uint32_t sm[];
    uint32_t (*Qh)[128][20] = reinterpret_cast<uint32_t(*)[128][20]>(sm);
    uint32_t (*Ql)[128][20] = reinterpret_cast<uint32_t(*)[128][20]>(sm + 5120);
    uint32_t (*Kh)[128][20] = reinterpret_cast<uint32_t(*)[128][20]>(sm + 10240);
    uint32_t (*Kl)[128][20] = reinterpret_cast<uint32_t(*)[128][20]>(sm + 15360);

    const int tid  = threadIdx.x;
    const int warp = tid >> 5, lane = tid & 31;
    const int g = lane >> 2, t = lane & 3;
    const int wm = warp & 3, wn = warp >> 2;
    const int z = blockIdx.z, h = z >> 1, b = z & 1, bh = b * HH + h;
    const int m_base = blockIdx.y * 128;
    const int n_base = blockIdx.x * 128;

    const uint32_t* qh = g_qh + (size_t)bh * SS * 64;
    const uint32_t* ql = g_ql + (size_t)bh * SS * 64;
    const uint32_t* kh = g_kh + (size_t)bh * SS * 64;
    const uint32_t* kl = g_kl + (size_t)bh * SS * 64;

    // ldmatrix lane -> (row offset, word offset) within a 16x8-word region
    const int ro = ((lane >> 3) & 1) * 8 + (lane & 7);
    const int wo = (lane >> 4) * 4;

    float acc[2][8][4];
#pragma unroll
    for (int i = 0; i < 2; i++)
#pragma unroll
        for (int j = 0; j < 8; j++)
#pragma unroll
            for (int c = 0; c < 4; c++) acc[i][j][c] = 0.0f;

    auto load_stage = [&](int st, int kc) {
        const int w0 = kc * 16;
#pragma unroll
        for (int i = 0; i < 2; i++) {
            int idx = tid + i * 256;
            int row = idx >> 2, q4 = (idx & 3) * 4;
            cp16(smaddr(&Qh[st][row][q4]), qh + (size_t)(m_base + row) * 64 + w0 + q4);
            cp16(smaddr(&Ql[st][row][q4]), ql + (size_t)(m_base + row) * 64 + w0 + q4);
            cp16(smaddr(&Kh[st][row][q4]), kh + (size_t)(n_base + row) * 64 + w0 + q4);
            cp16(smaddr(&Kl[st][row][q4]), kl + (size_t)(n_base + row) * 64 + w0 + q4);
        }
    };

    load_stage(0, 0);
    CP_COMMIT;

#pragma unroll 1
    for (int kc = 0; kc < 4; kc++) {
        const int C = kc & 1;
        if (kc < 3) load_stage(C ^ 1, kc + 1);
        CP_COMMIT;
        if (kc < 3) { CP_WAIT1; } else { CP_WAIT0; }
        __syncthreads();

#pragma unroll
        for (int ks = 0; ks < 2; ks++) {
            const int ko = ks * 8;
            uint32_t ah[2][4], al[2][4];
#pragma unroll
            for (int mt = 0; mt < 2; mt++) {
                int r = wm * 32 + mt * 16 + ro;
                ldsm4(ah[mt][0], ah[mt][1], ah[mt][2], ah[mt][3], smaddr(&Qh[C][r][ko + wo]));
                ldsm4(al[mt][0], al[mt][1], al[mt][2], al[mt][3], smaddr(&Ql[C][r][ko + wo]));
            }
#pragma unroll
            for (int np = 0; np < 4; np++) {
                int nr = wn * 64 + np * 16 + ro;
                uint32_t b0, b1, b2, b3, c0, c1, c2, c3;
                ldsm4(b0, b1, b2, b3, smaddr(&Kh[C][nr][ko + wo]));
                ldsm4(c0, c1, c2, c3, smaddr(&Kl[C][nr][ko + wo]));
#pragma unroll
                for (int mt = 0; mt < 2; mt++) {
                    MMA16816(acc[mt][np * 2],     ah[mt], b0, b2);
                    MMA16816(acc[mt][np * 2],     ah[mt], c0, c2);
                    MMA16816(acc[mt][np * 2],     al[mt], b0, b2);
                    MMA16816(acc[mt][np * 2 + 1], ah[mt], b1, b3);
                    MMA16816(acc[mt][np * 2 + 1], ah[mt], c1, c3);
                    MMA16816(acc[mt][np * 2 + 1], al[mt], b1, b3);
                }
            }
        }
        __syncthreads();
    }

    // --- epilogue: + bias, mask, write raw scores (q was pre-scaled) ---
    const float* biasb = bias + (size_t)h * SS * SS;
    const int*   maskb = mask + (size_t)b * SS * SS;
    float*       attnb = attn + (size_t)bh * SS * SS;

#pragma unroll
    for (int mt = 0; mt < 2; mt++) {
#pragma unroll
        for (int nt = 0; nt < 8; nt++) {
            int col  = n_base + wn * 64 + nt * 8 + 2 * t;
            int row0 = m_base + wm * 32 + mt * 16 + g;
#pragma unroll
            for (int half = 0; half < 2; half++) {
                int row = row0 + half * 8;
                float2 bb = *reinterpret_cast<const float2*>(biasb + (size_t)row * SS + col);
                int2   mm = *reinterpret_cast<const int2*>(maskb + (size_t)row * SS + col);
                float s0 = acc[mt][nt][half * 2 + 0] + bb.x;
                float s1 = acc[mt][nt][half * 2 + 1] + bb.y;
                if (mm.x == 0) s0 = -1e9f;
                if (mm.y == 0) s1 = -1e9f;
                *reinterpret_cast<float2*>(attnb + (size_t)row * SS + col) = make_float2(s0, s1);
            }
        }
    }
}

// ---------------------------------------------------------------------------
// Kernel 2: row softmax, in-place. One block (256 thr) per row.
// ---------------------------------------------------------------------------
__global__ __launch_bounds__(256)
void sdpa_softmax_kernel(float* __restrict__ attn)
{
    const size_t row = blockIdx.x;
    float4* p = reinterpret_cast<float4*>(attn + row * SS);
    const int tid = threadIdx.x;
    const int lane = tid & 31, wid = tid >> 5;

    float4 v1 = p[tid];
    float4 v2 = p[tid + 256];

    float m = fmaxf(fmaxf(fmaxf(v1.x, v1.y), fmaxf(v1.z, v1.w)),
                    fmaxf(fmaxf(v2.x, v2.y), fmaxf(v2.z, v2.w)));
#pragma unroll
    for (int o = 16; o > 0; o >>= 1) m = fmaxf(m, __shfl_xor_sync(0xFFFFFFFFu, m, o));

    __shared__ float rmax[8], rsum[8];
    if (lane == 0) rmax[wid] = m;
    __syncthreads();
    m = rmax[0];
#pragma unroll
    for (int j = 1; j < 8; j++) m = fmaxf(m, rmax[j]);

    float e0 = __expf(v1.x - m), e1 = __expf(v1.y - m);
    float e2 = __expf(v1.z - m), e3 = __expf(v1.w - m);
    float e4 = __expf(v2.x - m), e5 = __expf(v2.y - m);
    float e6 = __expf(v2.z - m), e7 = __expf(v2.w - m);

    float s = (e0 + e1) + (e2 + e3) + (e4 + e5) + (e6 + e7);
#pragma unroll
    for (int o = 16; o > 0; o >>= 1) s += __shfl_xor_sync(0xFFFFFFFFu, s, o);
    if (lane == 0) rsum[wid] = s;
    __syncthreads();
    s = rsum[0];
#pragma unroll
    for (int j = 1; j < 8; j++) s += rsum[j];

    float inv = 1.0f / s;
    p[tid]       = make_float4(e0 * inv, e1 * inv, e2 * inv, e3 * inv);
    p[tid + 256] = make_float4(e4 * inv, e5 * inv, e6 * inv, e7 * inv);
}

// ---------------------------------------------------------------------------
// Kernel 3: out = attn @ V. 128 rows x 128 cols, K=2048, k-chunk=32.
// attn fp32 staged via cp.async then converted; V pre-split/transposed.
// ---------------------------------------------------------------------------
__global__ __launch_bounds__(256, 2)
void sdpa_out2_kernel(const float* __restrict__ attn, float* __restrict__ out)
{
    extern __shared__ uint32_t sm[];
    float    (*Ar)[128][36] = reinterpret_cast<float(*)[128][36]>(sm);       // 2*128*36 = 9216 w
    uint32_t (*Ah)[20]      = reinterpret_cast<uint32_t(*)[20]>(sm + 9216);  // 2560 w
    uint32_t (*Al)[20]      = reinterpret_cast<uint32_t(*)[20]>(sm + 11776); // 2560 w
    uint32_t (*Bh)[128][20] = reinterpret_cast<uint32_t(*)[128][20]>(sm + 14336); // 5120 w
    uint32_t (*Bl)[128][20] = reinterpret_cast<uint32_t(*)[128][20]>(sm + 19456); // 5120 w

    const int tid  = threadIdx.x;
    const int warp = tid >> 5, lane = tid & 31;
    const int g = lane >> 2, t = lane & 3;
    const int wm = warp & 3, wn = warp >> 2;
    const int bh = blockIdx.z;
    const int m_base = blockIdx.y * 128;

    const float* ab = attn + (size_t)bh * SS * SS;
    const uint32_t* vh = g_vth + (size_t)bh * DD * (SS / 2);
    const uint32_t* vl = g_vtl + (size_t)bh * DD * (SS / 2);

    const int ro = ((lane >> 3) & 1) * 8 + (lane & 7);
    const int wo = (lane >> 4) * 4;

    float acc[2][8][4];
#pragma unroll
    for (int i = 0; i < 2; i++)
#pragma unroll
        for (int j = 0; j < 8; j++)
#pragma unroll
            for (int c = 0; c < 4; c++) acc[i][j][c] = 0.0f;

    auto load_stage = [&](int st, int kc) {
        // attn raw: 128 rows x 8 float4
#pragma unroll
        for (int i = 0; i < 4; i++) {
            int idx = tid + i * 256;
            int row = idx >> 3, f4 = (idx & 7) * 4;
            cp16(smaddr(&Ar[st][row][f4]), ab + (size_t)(m_base + row) * SS + kc * 32 + f4);
        }
        // V tiles: 128 d-rows x 4 uint4 each (hi + lo)
#pragma unroll
        for (int i = 0; i < 2; i++) {
            int idx = tid + i * 256;
            int d = idx >> 2, q4 = (idx & 3) * 4;
            cp16(smaddr(&Bh[st][d][q4]), vh + (size_t)d * (SS / 2) + kc * 16 + q4);
            cp16(smaddr(&Bl[st][d][q4]), vl + (size_t)d * (SS / 2) + kc * 16 + q4);
        }
    };

    load_stage(0, 0);
    CP_COMMIT;

#pragma unroll 1
    for (int kc = 0; kc < 64; kc++) {
        const int C = kc & 1;
        if (kc < 63) load_stage(C ^ 1, kc + 1);
        CP_COMMIT;
        if (kc < 63) { CP_WAIT1; } else { CP_WAIT0; }
        __syncthreads();

        // convert attn fp32 -> split bf16 words
#pragma unroll
        for (int i = 0; i < 4; i++) {
            int idx = tid + i * 256;
            int row = idx >> 3, f4 = idx & 7;
            float4 x = *reinterpret_cast<const float4*>(&Ar[C][row][f4 * 4]);
            uint32_t h0, l0, h1, l1;
            cvt_pair(x.x, x.y, h0, l0);
            cvt_pair(x.z, x.w, h1, l1);
            uint2 hh; hh.x = h0; hh.y = h1;
            uint2 ll; ll.x = l0; ll.y = l1;
            *reinterpret_cast<uint2*>(&Ah[row][f4 * 2]) = hh;
            *reinterpret_cast<uint2*>(&Al[row][f4 * 2]) = ll;
        }
        __syncthreads();

#pragma unroll
        for (int ks = 0; ks < 2; ks++) {
            const int ko = ks * 8;
            uint32_t ah[2][4], al[2][4];
#pragma unroll
            for (int mt = 0; mt < 2; mt++) {
                int r = wm * 32 + mt * 16 + ro;
                ldsm4(ah[mt][0], ah[mt][1], ah[mt][2], ah[mt][3], smaddr(&Ah[r][ko + wo]));
                ldsm4(al[mt][0], al[mt][1], al[mt][2], al[mt][3], smaddr(&Al[r][ko + wo]));
            }
#pragma unroll
            for (int np = 0; np < 4; np++) {
                int nr = wn * 64 + np * 16 + ro;
                uint32_t b0, b1, b2, b3, c0, c1, c2, c3;
                ldsm4(b0, b1, b2, b3, smaddr(&Bh[C][nr][ko + wo]));
                ldsm4(c0, c1, c2, c3, smaddr(&Bl[C][nr][ko + wo]));
#pragma unroll
                for (int mt = 0; mt < 2; mt++) {
                    MMA16816(acc[mt][np * 2],     ah[mt], b0, b2);
                    MMA16816(acc[mt][np * 2],     ah[mt], c0, c2);
                    MMA16816(acc[mt][np * 2],     al[mt], b0, b2);
                    MMA16816(acc[mt][np * 2 + 1], ah[mt], b1, b3);
                    MMA16816(acc[mt][np * 2 + 1], ah[mt], c1, c3);
                    MMA16816(acc[mt][np * 2 + 1], al[mt], b1, b3);
                }
            }
        }
        __syncthreads();
    }

    float* ob = out + (size_t)bh * SS * DD;
#pragma unroll
    for (int mt = 0; mt < 2; mt++) {
#pragma unroll
        for (int nt = 0; nt < 8; nt++) {
            int col  = wn * 64 + nt * 8 + 2 * t;
            int row0 = m_base + wm * 32 + mt * 16 + g;
#pragma unroll
            for (int half = 0; half < 2; half++) {
                int row = row0 + half * 8;
                *reinterpret_cast<float2*>(ob + (size_t)row * DD + col) =
                    make_float2(acc[mt][nt][half * 2], acc[mt][nt][half * 2 + 1]);
            }
        }
    }
}

// ---------------------------------------------------------------------------
// Launch
// ---------------------------------------------------------------------------
extern "C" void kernel_launch(void* const* d_in, const int* in_sizes, int n_in,
                              void* d_out, int out_size)
{
    const float* q    = (const float*)d_in[0];
    const float* k    = (const float*)d_in[1];
    const float* v    = (const float*)d_in[2];
    const int*   mask = (const int*)  d_in[3];
    const float* bias = (const float*)d_in[4];

    float* out  = (float*)d_out;                       // [B,H,S,D]
    float* attn = out + (size_t)BB * HH * SS * DD;     // [B,H,S,S]

    cudaFuncSetAttribute(sdpa_scores2_kernel,
                         cudaFuncAttributeMaxDynamicSharedMemorySize, 81920);
    cudaFuncSetAttribute(sdpa_out2_kernel,
                         cudaFuncAttributeMaxDynamicSharedMemorySize, 98304);

    split_qk_kernel<<<2048, 256>>>((const float4*)q, (const float4*)k);
    split_vt_kernel<<<dim3(SS / 64, BH), 256>>>(v);

    dim3 g1(SS / 128, SS / 128, BH);
    sdpa_scores2_kernel<<<g1, 256, 81920>>>(mask, bias, attn);

    sdpa_softmax_kernel<<<BH * SS, 256>>>(attn);

    dim3 g3(1, SS / 128, BH);
    sdpa_out2_kernel<<<g3, 256, 98304>>>(attn, out);
}